// round 12
// baseline (speedup 1.0000x reference)
#include <cuda_runtime.h>
#include <cuda_fp16.h>
#include <math.h>
#include <stdint.h>

#define DIM   768
#define HEADS 12
#define HD    64
#define NCLS  1000
#define NPAD  1024
#define BB    4
#define NN    2048
#define MM    (BB*NN)   // 8192

// ---------------- scratch ----------------
__device__ __half g_qkv[MM * 3 * DIM];
__device__ __half g_att[MM * DIM];
__device__ __half g_proj[MM * DIM];
__device__ __half g_vt[(size_t)BB * DIM * NN];
__device__ uint32_t g_maxu[BB * NCLS];
__device__ __half g_xh[MM * DIM];
__device__ __half g_wqkvT[3 * DIM * DIM];
__device__ __half g_wprojT[DIM * DIM];
__device__ __half g_wheadT[NPAD * DIM];

// ---------------- helpers ----------------
__device__ __forceinline__ uint32_t smaddr(const void* p){
    uint32_t a;
    asm("{ .reg .u64 t; cvta.to.shared.u64 t, %1; cvt.u32.u64 %0, t; }" : "=r"(a) : "l"(p));
    return a;
}
__device__ __forceinline__ uint32_t h2pack(float lo, float hi){
    __half2 h = __floats2half2_rn(lo, hi);
    return *reinterpret_cast<uint32_t*>(&h);
}
__device__ __forceinline__ uint32_t h2ex2(uint32_t x){
    uint32_t y; asm("ex2.approx.f16x2 %0, %1;" : "=r"(y) : "r"(x)); return y;
}
__device__ __forceinline__ void mma16(float* d, const uint32_t* a, const uint32_t* b){
    asm volatile(
      "mma.sync.aligned.m16n8k16.row.col.f32.f16.f16.f32 "
      "{%0,%1,%2,%3},{%4,%5,%6,%7},{%8,%9},{%0,%1,%2,%3};"
      : "+f"(d[0]), "+f"(d[1]), "+f"(d[2]), "+f"(d[3])
      : "r"(a[0]), "r"(a[1]), "r"(a[2]), "r"(a[3]), "r"(b[0]), "r"(b[1]));
}
__device__ __forceinline__ void ldsm4(uint32_t* r, uint32_t addr){
    asm volatile("ldmatrix.sync.aligned.m8n8.x4.shared.b16 {%0,%1,%2,%3}, [%4];"
      : "=r"(r[0]), "=r"(r[1]), "=r"(r[2]), "=r"(r[3]) : "r"(addr));
}
__device__ __forceinline__ void cp16(uint32_t dst, const void* src){
    asm volatile("cp.async.ca.shared.global [%0], [%1], 16;" :: "r"(dst), "l"(src));
}
#define CP_COMMIT asm volatile("cp.async.commit_group;")
#define CP_WAIT1  asm volatile("cp.async.wait_group 1;")
#define CP_WAIT2  asm volatile("cp.async.wait_group 2;")

__device__ __forceinline__ uint32_t fenc(float f){
    uint32_t u = __float_as_uint(f);
    return (u & 0x80000000u) ? ~u : (u | 0x80000000u);
}
__device__ __forceinline__ float fdec(uint32_t k){
    return (k & 0x80000000u) ? __uint_as_float(k & 0x7fffffffu) : __uint_as_float(~k);
}

// ---------------- fused preprocessing (single launch) ----------------
#define SCL2E 0.1803368801111204f   // (1/8) * log2(e)
#define NB_XH   6144
#define NB_WQ   (24*72)
#define NB_WP   (24*24)
#define NB_WH   (24*32)
#define NB_INIT 16
#define NB_TOTAL (NB_XH + NB_WQ + NB_WP + NB_WH + NB_INIT)

__device__ void wtrans_body(const float* __restrict__ src, __half* __restrict__ dst,
                            int K, int N, int Npad, int scaleN, float sc,
                            int kb, int nb, int tid)
{
    __shared__ float tile[32][33];
    int tx = tid & 31, ty = tid >> 5;
#pragma unroll
    for (int i = 0; i < 32; i += 8){
        int k = kb + ty + i, n = nb + tx;
        float v = 0.f;
        if (k < K && n < N) v = src[(size_t)k * N + n];
        tile[ty + i][tx] = v;
    }
    __syncthreads();
#pragma unroll
    for (int i = 0; i < 32; i += 8){
        int n = nb + ty + i, k = kb + tx;
        if (n < Npad && k < K){
            float v = tile[tx][ty + i];
            if (n < scaleN) v *= sc;
            dst[(size_t)n * K + k] = __float2half_rn(v);
        }
    }
}

__global__ void prep(const float* __restrict__ x,
                     const float* __restrict__ wq, const float* __restrict__ wp,
                     const float* __restrict__ wh,
                     __half* __restrict__ xh, __half* __restrict__ wqT,
                     __half* __restrict__ wpT, __half* __restrict__ whT,
                     uint32_t* __restrict__ mxu)
{
    int bx = blockIdx.x, tid = threadIdx.x;
    if (bx < NB_XH){
        int i = bx * 256 + tid;
        float4 v = ((const float4*)x)[i];
        ((uint2*)xh)[i] = make_uint2(h2pack(v.x, v.y), h2pack(v.z, v.w));
    } else if (bx < NB_XH + NB_WQ){
        int bb = bx - NB_XH;
        wtrans_body(wq, wqT, DIM, 3*DIM, 3*DIM, DIM, SCL2E, (bb % 24)*32, (bb / 24)*32, tid);
    } else if (bx < NB_XH + NB_WQ + NB_WP){
        int bb = bx - NB_XH - NB_WQ;
        wtrans_body(wp, wpT, DIM, DIM, DIM, 0, 1.f, (bb % 24)*32, (bb / 24)*32, tid);
    } else if (bx < NB_XH + NB_WQ + NB_WP + NB_WH){
        int bb = bx - NB_XH - NB_WQ - NB_WP;
        wtrans_body(wh, whT, DIM, NCLS, NPAD, 0, 1.f, (bb % 24)*32, (bb / 24)*32, tid);
    } else {
        int bb = bx - (NB_XH + NB_WQ + NB_WP + NB_WH);
        int i = bb * 256 + tid;
        if (i < BB * NCLS) mxu[i] = 0u;
    }
}

__global__ void decode_maxu(const uint32_t* __restrict__ buf, float* __restrict__ out){
    int i = blockIdx.x * blockDim.x + threadIdx.x;
    if (i < BB * NCLS) out[i] = fdec(buf[i]);
}

// ======== FP16 GEMM: 64x128 CTA tile, warp 32x32, 3-stage cp.async ========
// 8 warps: wm = (wid&1)*32, wn = (wid>>1)*32. acc = 32 f32/thread (no spills).
// MODE 1: store half (+bias). MODE 2: fused column-max. MODE 3: fused QKV with
// d-major V store for n0 >= 2*DIM.
#define PAH2 72
#define ASTG (64*PAH2*2)                // 9216 B
#define BSTG (128*PAH2*2)               // 18432 B
#define STG  (ASTG + BSTG)              // 27648 B per stage
#define GEMM_SMEM (3*STG)               // 82944 B; 2 CTAs = 166KB
#define SP 72                           // V-transpose stage stride (64 tokens + pad)

template<int MODE>
__global__ __launch_bounds__(256, 2)
void mma_gemm(const __half* __restrict__ A, const __half* __restrict__ Bt,
              const float* __restrict__ bias, __half* __restrict__ C,
              uint32_t* __restrict__ maxbuf, __half* __restrict__ Vt,
              int M, int N, int K)
{
    extern __shared__ char smc[];
    const uint32_t smb = smaddr(smc);

    const int tid = threadIdx.x;
    const int wid = tid >> 5, lane = tid & 31;
    const int g = lane >> 2, t = lane & 3;
    const int wm = (wid & 1) * 32, wn = (wid >> 1) * 32;
    const int m0 = blockIdx.y * 64, n0 = blockIdx.x * 128;

    const uint32_t aLane = (uint32_t)((((lane & 15) + wm) * PAH2 + (lane >> 4) * 8) * 2);
    const uint32_t bLane = (uint32_t)(((lane & 7) * PAH2 + (lane >> 3) * 8) * 2);

    float acc[2][4][4];
#pragma unroll
    for (int i = 0; i < 2; i++)
#pragma unroll
        for (int j = 0; j < 4; j++)
#pragma unroll
            for (int k = 0; k < 4; k++) acc[i][j][k] = 0.f;

    const int KT = K / 64;   // 12

    auto fill = [&](int chunk, int s){
        const int k0 = chunk * 64;
        const uint32_t sa = smb + (uint32_t)(s * STG);
        const uint32_t sb = sa + ASTG;
#pragma unroll
        for (int i = 0; i < 2; i++){             // A: 64 rows
            int idx = tid + i*256;
            int r = idx >> 3, c = (idx & 7) * 8;
            cp16(sa + (uint32_t)((r*PAH2 + c)*2), A + (size_t)(m0+r)*K + k0 + c);
        }
#pragma unroll
        for (int i = 0; i < 4; i++){             // B: 128 rows
            int idx = tid + i*256;
            int r = idx >> 3, c = (idx & 7) * 8;
            cp16(sb + (uint32_t)((r*PAH2 + c)*2), Bt + (size_t)(n0+r)*K + k0 + c);
        }
        CP_COMMIT;
    };

    fill(0, 0); fill(1, 1);

    for (int kt = 0; kt < KT; ++kt){
        CP_WAIT1; __syncthreads();
        int st = kt % 3;
        if (kt + 2 < KT) fill(kt + 2, (kt + 2) % 3);
        else             { CP_COMMIT; }

        const uint32_t aA = smb + (uint32_t)(st*STG) + aLane;
        const uint32_t bA = smb + (uint32_t)(st*STG + ASTG) + bLane;

#pragma unroll
        for (int hf = 0; hf < 2; ++hf){
            uint32_t bfr[4][4];
#pragma unroll
            for (int na = 0; na < 4; ++na)
                ldsm4(bfr[na], bA + (uint32_t)((wn + na*8)*PAH2*2 + hf*64));
#pragma unroll
            for (int kc = 0; kc < 2; ++kc){
                uint32_t af[2][4];
#pragma unroll
                for (int ma = 0; ma < 2; ++ma)
                    ldsm4(af[ma], aA + (uint32_t)(ma*16*PAH2*2 + (hf*2+kc)*32));
#pragma unroll
                for (int na = 0; na < 4; ++na)
#pragma unroll
                    for (int ma = 0; ma < 2; ++ma)
                        mma16(acc[ma][na], af[ma], bfr[na] + kc*2);
            }
        }
    }

    if (MODE == 3 && n0 >= 2*DIM){
        // ---- d-major (transposed) store to Vt via smem staging ----
        __syncthreads();
        __half* stage = (__half*)smc;            // [128 d][SP]
#pragma unroll
        for (int na = 0; na < 4; ++na){
            int cl = wn + na*8 + 2*t;
#pragma unroll
            for (int ma = 0; ma < 2; ++ma){
                int rl = wm + ma*16 + g;
                stage[(cl  )*SP + rl    ] = __float2half_rn(acc[ma][na][0]);
                stage[(cl+1)*SP + rl    ] = __float2half_rn(acc[ma][na][1]);
                stage[(cl  )*SP + rl + 8] = __float2half_rn(acc[ma][na][2]);
                stage[(cl+1)*SP + rl + 8] = __float2half_rn(acc[ma][na][3]);
            }
        }
        __syncthreads();
        const int bq   = m0 >> 11;
        const int tok0 = m0 & (NN - 1);
        const int d0   = n0 - 2*DIM;
#pragma unroll
        for (int i = 0; i < 4; i++){
            int j = tid + i*256;                 // 0..1023: 128 d x 8 segs
            int d = j >> 3, seg = j & 7;
            uint4 v = *(uint4*)(stage + d*SP + seg*8);
            *(uint4*)(Vt + ((size_t)(bq*DIM + d0 + d))*NN + tok0 + seg*8) = v;
        }
    } else if (MODE == 2){
        const int bidx = m0 >> 11;
#pragma unroll
        for (int na = 0; na < 4; ++na){
            int cc = n0 + wn + na*8 + 2*t;
            float m0v = -INFINITY, m1v = -INFINITY;
#pragma unroll
            for (int ma = 0; ma < 2; ++ma){
                m0v = fmaxf(m0v, fmaxf(acc[ma][na][0], acc[ma][na][2]));
                m1v = fmaxf(m1v, fmaxf(acc[ma][na][1], acc[ma][na][3]));
            }
#pragma unroll
            for (int off = 4; off < 32; off <<= 1){
                m0v = fmaxf(m0v, __shfl_xor_sync(0xffffffffu, m0v, off));
                m1v = fmaxf(m1v, __shfl_xor_sync(0xffffffffu, m1v, off));
            }
            if (g == 0 && cc < NCLS){
                atomicMax(&maxbuf[bidx*NCLS + cc],     fenc(m0v + bias[cc]));
                atomicMax(&maxbuf[bidx*NCLS + cc + 1], fenc(m1v + bias[cc+1]));
            }
        }
    } else {
#pragma unroll
        for (int na = 0; na < 4; ++na){
            int cc = n0 + wn + na*8 + 2*t;
            float b0 = 0.f, b1 = 0.f;
            if (bias){ b0 = bias[cc]; b1 = bias[cc+1]; }
#pragma unroll
            for (int ma = 0; ma < 2; ++ma){
                int r = m0 + wm + ma*16 + g;
                *(uint32_t*)&C[(size_t)r*N + cc]     = h2pack(acc[ma][na][0]+b0, acc[ma][na][1]+b1);
                *(uint32_t*)&C[(size_t)(r+8)*N + cc] = h2pack(acc[ma][na][2]+b0, acc[ma][na][3]+b1);
            }
        }
    }
}

// ===== FP16 flash attention: interleaved S->P->PV halves, constant ones-frag =====
#define QP 72
#define KP 72
#define VP 72
#define OFF_Q 0
#define OFF_K (128*QP)                        // 9216 halves
#define OFF_V (OFF_K + 3*64*KP)               // K: 3 stages x 64 rows
#define ATT_HALVES (OFF_V + 3*64*VP)
#define ATT_SMEM (ATT_HALVES*2)               // 73728 B

__global__ __launch_bounds__(256, 2)
void attn_mma(const __half* __restrict__ qkv, const __half* __restrict__ vt,
              __half* __restrict__ out)
{
    extern __shared__ char smc[];
    const uint32_t smb = smaddr(smc);

    const int b = blockIdx.y / HEADS, h = blockIdx.y % HEADS;
    const int q0 = blockIdx.x * 128;
    const int tid = threadIdx.x, wid = tid >> 5, lane = tid & 31;
    const int g = lane >> 2, t = lane & 3;

    const uint32_t qLane = (uint32_t)(((wid*16 + (lane & 15))*QP + (lane >> 4)*8) * 2);
    const uint32_t bLaneK = (uint32_t)(((lane & 7)*KP + (lane >> 3)*8) * 2);
    const uint32_t bLaneV = (uint32_t)(((lane & 7)*VP + (lane >> 3)*8) * 2);

    const __half* base  = qkv + (size_t)(b*NN)*(3*DIM) + h*HD;
    const __half* vbase = vt  + ((size_t)b*DIM + h*HD) * NN;

    const uint32_t vone = (g == 0) ? 0x3C003C00u : 0u;
    const uint32_t cone[2] = { vone, vone };

#pragma unroll
    for (int i = 0; i < 4; i++){
        int idx = tid + i*256;
        int r = idx >> 3, c = (idx & 7) * 8;
        cp16(smb + (uint32_t)((OFF_Q + r*QP + c)*2), base + (size_t)(q0+r)*(3*DIM) + c);
    }
    CP_COMMIT;

    auto fillkv = [&](int kt, int s){
        const int kv0 = kt * 64;
#pragma unroll
        for (int i = 0; i < 2; i++){
            int idx = tid + i*256;
            int r = idx >> 3, c = (idx & 7) * 8;
            cp16(smb + (uint32_t)((OFF_K + (s*64+r)*KP + c)*2), base  + (size_t)(kv0+r)*(3*DIM) + DIM + c);
            cp16(smb + (uint32_t)((OFF_V + (s*64+r)*VP + c)*2), vbase + (size_t)r*NN + kv0 + c);
        }
        CP_COMMIT;
    };

    fillkv(0, 0); fillkv(1, 1);

    CP_WAIT2; __syncthreads();
    uint32_t qf[4][4];
#pragma unroll
    for (int kc = 0; kc < 4; kc++)
        ldsm4(qf[kc], smb + qLane + (uint32_t)(kc*32));

    float o[8][4], o_l[4];
#pragma unroll
    for (int i = 0; i < 8; i++)
#pragma unroll
        for (int j = 0; j < 4; j++) o[i][j] = 0.f;
#pragma unroll
    for (int j = 0; j < 4; j++) o_l[j] = 0.f;

    const int NT = NN/64;   // 32
    for (int kt = 0; kt < NT; ++kt){
        CP_WAIT1; __syncthreads();
        int st = kt % 3;
        if (kt + 2 < NT) fillkv(kt + 2, (kt + 2) % 3);
        else             { CP_COMMIT; }

        const uint32_t kA = smb + (uint32_t)((OFF_K + st*64*KP)*2) + bLaneK;
        const uint32_t vA = smb + (uint32_t)((OFF_V + st*64*VP)*2) + bLaneV;

#pragma unroll
        for (int jp2 = 0; jp2 < 2; ++jp2){
            float s[4][4];
#pragma unroll
            for (int i = 0; i < 4; i++)
#pragma unroll
                for (int j = 0; j < 4; j++) s[i][j] = 0.f;
#pragma unroll
            for (int na4 = 0; na4 < 4; ++na4){
                int na = jp2*4 + na4;
                uint32_t bf0[4], bf1[4];
                ldsm4(bf0, kA + (uint32_t)(na*8*KP*2));
                ldsm4(bf1, kA + (uint32_t)(na*8*KP*2 + 64));
                mma16(s[na4], qf[0], bf0);
                mma16(s[na4], qf[1], bf0 + 2);
                mma16(s[na4], qf[2], bf1);
                mma16(s[na4], qf[3], bf1 + 2);
            }

            uint32_t pf[2][4];
            pf[0][0] = h2ex2(h2pack(s[0][0], s[0][1]));
            pf[0][1] = h2ex2(h2pack(s[0][2], s[0][3]));
            pf[0][2] = h2ex2(h2pack(s[1][0], s[1][1]));
            pf[0][3] = h2ex2(h2pack(s[1][2], s[1][3]));
            pf[1][0] = h2ex2(h2pack(s[2][0], s[2][1]));
            pf[1][1] = h2ex2(h2pack(s[2][2], s[2][3]));
            pf[1][2] = h2ex2(h2pack(s[3][0], s[3][1]));
            pf[1][3] = h2ex2(h2pack(s[3][2], s[3][3]));

            mma16(o_l, pf[0], cone);
            mma16(o_l, pf[1], cone);

#pragma unroll
            for (int nb = 0; nb < 8; ++nb){
                uint32_t vf[4];
                ldsm4(vf, vA + (uint32_t)(nb*8*VP*2 + jp2*64));
                mma16(o[nb], pf[0], vf);
                mma16(o[nb], pf[1], vf + 2);
            }
        }
    }

    float l0 = __shfl_sync(0xffffffffu, o_l[0], lane & ~3);
    float l1 = __shfl_sync(0xffffffffu, o_l[2], lane & ~3);
    float inv0 = 1.f / l0, inv1 = 1.f / l1;

    int r0 = b*NN + q0 + wid*16 + g;
#pragma unroll
    for (int na = 0; na < 8; na++){
        int cc = h*HD + na*8 + 2*t;
        *(uint32_t*)&out[(size_t)r0*DIM + cc]     = h2pack(o[na][0]*inv0, o[na][1]*inv0);
        *(uint32_t*)&out[(size_t)(r0+8)*DIM + cc] = h2pack(o[na][2]*inv1, o[na][3]*inv1);
    }
}

// ---------------- launch ----------------
extern "C" void kernel_launch(void* const* d_in, const int* in_sizes, int n_in,
                              void* d_out, int out_size)
{
    const float* x      = (const float*)d_in[0];
    const float* w_qkv  = (const float*)d_in[1];
    const float* w_proj = (const float*)d_in[2];
    const float* b_proj = (const float*)d_in[3];
    const float* w_head = (const float*)d_in[4];
    const float* b_head = (const float*)d_in[5];
    float* out = (float*)d_out;

    __half *qkv, *att, *proj, *vt, *xh, *wqT, *wpT, *whT;
    uint32_t* mxu;
    cudaGetSymbolAddress((void**)&qkv, g_qkv);
    cudaGetSymbolAddress((void**)&att, g_att);
    cudaGetSymbolAddress((void**)&proj, g_proj);
    cudaGetSymbolAddress((void**)&vt,  g_vt);
    cudaGetSymbolAddress((void**)&xh,  g_xh);
    cudaGetSymbolAddress((void**)&wqT, g_wqkvT);
    cudaGetSymbolAddress((void**)&wpT, g_wprojT);
    cudaGetSymbolAddress((void**)&whT, g_wheadT);
    cudaGetSymbolAddress((void**)&mxu, g_maxu);

    cudaFuncSetAttribute(mma_gemm<1>, cudaFuncAttributeMaxDynamicSharedMemorySize, GEMM_SMEM);
    cudaFuncSetAttribute(mma_gemm<2>, cudaFuncAttributeMaxDynamicSharedMemorySize, GEMM_SMEM);
    cudaFuncSetAttribute(mma_gemm<3>, cudaFuncAttributeMaxDynamicSharedMemorySize, GEMM_SMEM);
    cudaFuncSetAttribute(attn_mma,    cudaFuncAttributeMaxDynamicSharedMemorySize, ATT_SMEM);

    // 1) fused preprocessing
    prep<<<NB_TOTAL, 256>>>(x, w_qkv, w_proj, w_head, xh, wqT, wpT, whT, mxu);

    // 2) QKV GEMM — Q,K row-major to qkv; V d-major to vt
    mma_gemm<3><<<dim3(3*DIM/128, MM/64), 256, GEMM_SMEM>>>(
        xh, wqT, nullptr, qkv, nullptr, vt, MM, 3*DIM, DIM);

    // 3) attention
    attn_mma<<<dim3(NN/128, BB*HEADS), 256, ATT_SMEM>>>(qkv, vt, att);

    // 4) proj GEMM
    mma_gemm<1><<<dim3(DIM/128, MM/64), 256, GEMM_SMEM>>>(
        att, wpT, b_proj, proj, nullptr, nullptr, MM, DIM, DIM);

    // 5) head GEMM + fused token-max
    mma_gemm<2><<<dim3(NPAD/128, MM/64), 256, GEMM_SMEM>>>(
        proj, whT, b_head, nullptr, mxu, nullptr, MM, NPAD, DIM);

    // 6) decode
    decode_maxu<<<(BB*NCLS + 255)/256, 256>>>(mxu, out);
}

// round 16
// speedup vs baseline: 1.0700x; 1.0700x over previous
#include <cuda_runtime.h>
#include <cuda_fp16.h>
#include <math.h>
#include <stdint.h>

#define DIM   768
#define HEADS 12
#define HD    64
#define NCLS  1000
#define NPAD  1024
#define BB    4
#define NN    2048
#define MM    (BB*NN)   // 8192

// ---------------- scratch ----------------
__device__ __half g_qkv[MM * 3 * DIM];
__device__ __half g_att[MM * DIM];
__device__ __half g_proj[MM * DIM];
__device__ __half g_vt[(size_t)BB * DIM * NN];
__device__ uint32_t g_maxu[BB * NCLS];
__device__ __half g_xh[MM * DIM];
__device__ __half g_wqkvT[3 * DIM * DIM];
__device__ __half g_wprojT[DIM * DIM];
__device__ __half g_wheadT[NPAD * DIM];

// ---------------- helpers ----------------
__device__ __forceinline__ uint32_t smaddr(const void* p){
    uint32_t a;
    asm("{ .reg .u64 t; cvta.to.shared.u64 t, %1; cvt.u32.u64 %0, t; }" : "=r"(a) : "l"(p));
    return a;
}
__device__ __forceinline__ uint32_t h2pack(float lo, float hi){
    __half2 h = __floats2half2_rn(lo, hi);
    return *reinterpret_cast<uint32_t*>(&h);
}
__device__ __forceinline__ uint32_t h2ex2(uint32_t x){
    uint32_t y; asm("ex2.approx.f16x2 %0, %1;" : "=r"(y) : "r"(x)); return y;
}
__device__ __forceinline__ void mma16(float* d, const uint32_t* a, const uint32_t* b){
    asm volatile(
      "mma.sync.aligned.m16n8k16.row.col.f32.f16.f16.f32 "
      "{%0,%1,%2,%3},{%4,%5,%6,%7},{%8,%9},{%0,%1,%2,%3};"
      : "+f"(d[0]), "+f"(d[1]), "+f"(d[2]), "+f"(d[3])
      : "r"(a[0]), "r"(a[1]), "r"(a[2]), "r"(a[3]), "r"(b[0]), "r"(b[1]));
}
__device__ __forceinline__ void ldsm4(uint32_t* r, uint32_t addr){
    asm volatile("ldmatrix.sync.aligned.m8n8.x4.shared.b16 {%0,%1,%2,%3}, [%4];"
      : "=r"(r[0]), "=r"(r[1]), "=r"(r[2]), "=r"(r[3]) : "r"(addr));
}
// L2-only caching: tile data is staged to smem and never re-read through L1.
__device__ __forceinline__ void cp16(uint32_t dst, const void* src){
    asm volatile("cp.async.cg.shared.global [%0], [%1], 16;" :: "r"(dst), "l"(src));
}
#define CP_COMMIT asm volatile("cp.async.commit_group;")
#define CP_WAIT1  asm volatile("cp.async.wait_group 1;")
#define CP_WAIT2  asm volatile("cp.async.wait_group 2;")

__device__ __forceinline__ uint32_t fenc(float f){
    uint32_t u = __float_as_uint(f);
    return (u & 0x80000000u) ? ~u : (u | 0x80000000u);
}
__device__ __forceinline__ float fdec(uint32_t k){
    return (k & 0x80000000u) ? __uint_as_float(k & 0x7fffffffu) : __uint_as_float(~k);
}

// ---------------- fused preprocessing (single launch) ----------------
#define SCL2E 0.1803368801111204f   // (1/8) * log2(e)
#define NB_XH   6144
#define NB_WQ   (24*72)
#define NB_WP   (24*24)
#define NB_WH   (24*32)
#define NB_INIT 16
#define NB_TOTAL (NB_XH + NB_WQ + NB_WP + NB_WH + NB_INIT)

__device__ void wtrans_body(const float* __restrict__ src, __half* __restrict__ dst,
                            int K, int N, int Npad, int scaleN, float sc,
                            int kb, int nb, int tid)
{
    __shared__ float tile[32][33];
    int tx = tid & 31, ty = tid >> 5;
#pragma unroll
    for (int i = 0; i < 32; i += 8){
        int k = kb + ty + i, n = nb + tx;
        float v = 0.f;
        if (k < K && n < N) v = src[(size_t)k * N + n];
        tile[ty + i][tx] = v;
    }
    __syncthreads();
#pragma unroll
    for (int i = 0; i < 32; i += 8){
        int n = nb + ty + i, k = kb + tx;
        if (n < Npad && k < K){
            float v = tile[tx][ty + i];
            if (n < scaleN) v *= sc;
            dst[(size_t)n * K + k] = __float2half_rn(v);
        }
    }
}

__global__ void prep(const float* __restrict__ x,
                     const float* __restrict__ wq, const float* __restrict__ wp,
                     const float* __restrict__ wh,
                     __half* __restrict__ xh, __half* __restrict__ wqT,
                     __half* __restrict__ wpT, __half* __restrict__ whT,
                     uint32_t* __restrict__ mxu)
{
    int bx = blockIdx.x, tid = threadIdx.x;
    if (bx < NB_XH){
        int i = bx * 256 + tid;
        float4 v = ((const float4*)x)[i];
        ((uint2*)xh)[i] = make_uint2(h2pack(v.x, v.y), h2pack(v.z, v.w));
    } else if (bx < NB_XH + NB_WQ){
        int bb = bx - NB_XH;
        wtrans_body(wq, wqT, DIM, 3*DIM, 3*DIM, DIM, SCL2E, (bb % 24)*32, (bb / 24)*32, tid);
    } else if (bx < NB_XH + NB_WQ + NB_WP){
        int bb = bx - NB_XH - NB_WQ;
        wtrans_body(wp, wpT, DIM, DIM, DIM, 0, 1.f, (bb % 24)*32, (bb / 24)*32, tid);
    } else if (bx < NB_XH + NB_WQ + NB_WP + NB_WH){
        int bb = bx - NB_XH - NB_WQ - NB_WP;
        wtrans_body(wh, whT, DIM, NCLS, NPAD, 0, 1.f, (bb % 24)*32, (bb / 24)*32, tid);
    } else {
        int bb = bx - (NB_XH + NB_WQ + NB_WP + NB_WH);
        int i = bb * 256 + tid;
        if (i < BB * NCLS) mxu[i] = 0u;
    }
}

__global__ void decode_maxu(const uint32_t* __restrict__ buf, float* __restrict__ out){
    int i = blockIdx.x * blockDim.x + threadIdx.x;
    if (i < BB * NCLS) out[i] = fdec(buf[i]);
}

// ======== FP16 GEMM: 128x128x64 chunks (R11 tile), 3-stage cp.async.cg ========
// MODE 1: store half (+bias). MODE 2: fused column-max. MODE 3: fused QKV —
// n-blocks in the V third store TRANSPOSED (d-major) to Vt; others store to C.
#define PAH2 72
#define GSTG2 (128*PAH2*2)              // 18432 B
#define GEMM_SMEM (6*GSTG2)             // 110592 B
#define SP 136                          // transpose-stage stride (halves)

template<int MODE>
__global__ __launch_bounds__(256, 2)
void mma_gemm(const __half* __restrict__ A, const __half* __restrict__ Bt,
              const float* __restrict__ bias, __half* __restrict__ C,
              uint32_t* __restrict__ maxbuf, __half* __restrict__ Vt,
              int M, int N, int K)
{
    extern __shared__ char smc[];
    const uint32_t smb = smaddr(smc);

    const int tid = threadIdx.x;
    const int wid = tid >> 5, lane = tid & 31;
    const int g = lane >> 2, t = lane & 3;
    const int wm = (wid >> 2) * 64, wn = (wid & 3) * 32;
    const int m0 = blockIdx.y * 128, n0 = blockIdx.x * 128;

    const uint32_t aLane = (uint32_t)((((lane & 15) + wm) * PAH2 + (lane >> 4) * 8) * 2);
    const uint32_t bLane = (uint32_t)(((lane & 7) * PAH2 + (lane >> 3) * 8) * 2);

    float acc[4][4][4];
#pragma unroll
    for (int i = 0; i < 4; i++)
#pragma unroll
        for (int j = 0; j < 4; j++)
#pragma unroll
            for (int k = 0; k < 4; k++) acc[i][j][k] = 0.f;

    const int KT = K / 64;   // 12

    auto fill = [&](int chunk, int s){
        const int k0 = chunk * 64;
        const uint32_t sa = smb + (uint32_t)(s * 2 * GSTG2);
        const uint32_t sb = sa + GSTG2;
#pragma unroll
        for (int i = 0; i < 4; i++){
            int idx = tid + i*256;
            int r = idx >> 3, c = (idx & 7) * 8;
            cp16(sa + (uint32_t)((r*PAH2 + c)*2), A  + (size_t)(m0+r)*K + k0 + c);
            cp16(sb + (uint32_t)((r*PAH2 + c)*2), Bt + (size_t)(n0+r)*K + k0 + c);
        }
        CP_COMMIT;
    };

    fill(0, 0); fill(1, 1);

    for (int kt = 0; kt < KT; ++kt){
        CP_WAIT1; __syncthreads();
        int st = kt % 3;
        if (kt + 2 < KT) fill(kt + 2, (kt + 2) % 3);
        else             { CP_COMMIT; }

        const uint32_t aA = smb + (uint32_t)(st*2*GSTG2) + aLane;
        const uint32_t bA = smb + (uint32_t)(st*2*GSTG2 + GSTG2) + bLane;

#pragma unroll
        for (int hf = 0; hf < 2; ++hf){
            uint32_t bfr[4][4];
#pragma unroll
            for (int na = 0; na < 4; ++na)
                ldsm4(bfr[na], bA + (uint32_t)((wn + na*8)*PAH2*2 + hf*64));
#pragma unroll
            for (int kc = 0; kc < 2; ++kc){
                uint32_t af[4][4];
#pragma unroll
                for (int ma = 0; ma < 4; ++ma)
                    ldsm4(af[ma], aA + (uint32_t)(ma*16*PAH2*2 + (hf*2+kc)*32));
#pragma unroll
                for (int na = 0; na < 4; ++na)
#pragma unroll
                    for (int ma = 0; ma < 4; ++ma)
                        mma16(acc[ma][na], af[ma], bfr[na] + kc*2);
            }
        }
    }

    if (MODE == 3 && n0 >= 2*DIM){
        // ---- d-major (transposed) store to Vt via smem staging ----
        __syncthreads();
        __half* stage = (__half*)smc;
#pragma unroll
        for (int na = 0; na < 4; ++na){
            int cl = wn + na*8 + 2*t;
#pragma unroll
            for (int ma = 0; ma < 4; ++ma){
                int rl = wm + ma*16 + g;
                stage[(cl  )*SP + rl    ] = __float2half_rn(acc[ma][na][0]);
                stage[(cl+1)*SP + rl    ] = __float2half_rn(acc[ma][na][1]);
                stage[(cl  )*SP + rl + 8] = __float2half_rn(acc[ma][na][2]);
                stage[(cl+1)*SP + rl + 8] = __float2half_rn(acc[ma][na][3]);
            }
        }
        __syncthreads();
        const int bq   = m0 >> 11;
        const int tok0 = m0 & (NN - 1);
        const int d0   = n0 - 2*DIM;
#pragma unroll
        for (int i = 0; i < 8; i++){
            int j = tid + i*256;
            int d = j >> 4, seg = j & 15;
            uint4 v = *(uint4*)(stage + d*SP + seg*8);
            *(uint4*)(Vt + ((size_t)(bq*DIM + d0 + d))*NN + tok0 + seg*8) = v;
        }
    } else if (MODE == 2){
        const int bidx = blockIdx.y >> 4;
#pragma unroll
        for (int na = 0; na < 4; ++na){
            int cc = n0 + wn + na*8 + 2*t;
            float m0v = -INFINITY, m1v = -INFINITY;
#pragma unroll
            for (int ma = 0; ma < 4; ++ma){
                m0v = fmaxf(m0v, fmaxf(acc[ma][na][0], acc[ma][na][2]));
                m1v = fmaxf(m1v, fmaxf(acc[ma][na][1], acc[ma][na][3]));
            }
#pragma unroll
            for (int off = 4; off < 32; off <<= 1){
                m0v = fmaxf(m0v, __shfl_xor_sync(0xffffffffu, m0v, off));
                m1v = fmaxf(m1v, __shfl_xor_sync(0xffffffffu, m1v, off));
            }
            if (g == 0 && cc < NCLS){
                atomicMax(&maxbuf[bidx*NCLS + cc],     fenc(m0v + bias[cc]));
                atomicMax(&maxbuf[bidx*NCLS + cc + 1], fenc(m1v + bias[cc+1]));
            }
        }
    } else {
#pragma unroll
        for (int na = 0; na < 4; ++na){
            int cc = n0 + wn + na*8 + 2*t;
            float b0 = 0.f, b1 = 0.f;
            if (bias){ b0 = bias[cc]; b1 = bias[cc+1]; }
#pragma unroll
            for (int ma = 0; ma < 4; ++ma){
                int r = m0 + wm + ma*16 + g;
                *(uint32_t*)&C[(size_t)r*N + cc]     = h2pack(acc[ma][na][0]+b0, acc[ma][na][1]+b1);
                *(uint32_t*)&C[(size_t)(r+8)*N + cc] = h2pack(acc[ma][na][2]+b0, acc[ma][na][3]+b1);
            }
        }
    }
}

// ===== FP16 flash attention: interleaved S->P->PV halves, constant ones-frag =====
#define QP 72
#define KP 72
#define VP 72
#define OFF_Q 0
#define OFF_K (128*QP)                        // 9216 halves
#define OFF_V (OFF_K + 3*64*KP)               // K: 3 stages x 64 rows
#define ATT_HALVES (OFF_V + 3*64*VP)
#define ATT_SMEM (ATT_HALVES*2)               // 73728 B

__global__ __launch_bounds__(256, 2)
void attn_mma(const __half* __restrict__ qkv, const __half* __restrict__ vt,
              __half* __restrict__ out)
{
    extern __shared__ char smc[];
    const uint32_t smb = smaddr(smc);

    const int b = blockIdx.y / HEADS, h = blockIdx.y % HEADS;
    const int q0 = blockIdx.x * 128;
    const int tid = threadIdx.x, wid = tid >> 5, lane = tid & 31;
    const int g = lane >> 2, t = lane & 3;

    const uint32_t qLane = (uint32_t)(((wid*16 + (lane & 15))*QP + (lane >> 4)*8) * 2);
    const uint32_t bLaneK = (uint32_t)(((lane & 7)*KP + (lane >> 3)*8) * 2);
    const uint32_t bLaneV = (uint32_t)(((lane & 7)*VP + (lane >> 3)*8) * 2);

    const __half* base  = qkv + (size_t)(b*NN)*(3*DIM) + h*HD;
    const __half* vbase = vt  + ((size_t)b*DIM + h*HD) * NN;

    const uint32_t vone = (g == 0) ? 0x3C003C00u : 0u;
    const uint32_t cone[2] = { vone, vone };

#pragma unroll
    for (int i = 0; i < 4; i++){
        int idx = tid + i*256;
        int r = idx >> 3, c = (idx & 7) * 8;
        cp16(smb + (uint32_t)((OFF_Q + r*QP + c)*2), base + (size_t)(q0+r)*(3*DIM) + c);
    }
    CP_COMMIT;

    auto fillkv = [&](int kt, int s){
        const int kv0 = kt * 64;
#pragma unroll
        for (int i = 0; i < 2; i++){
            int idx = tid + i*256;
            int r = idx >> 3, c = (idx & 7) * 8;
            cp16(smb + (uint32_t)((OFF_K + (s*64+r)*KP + c)*2), base  + (size_t)(kv0+r)*(3*DIM) + DIM + c);
            cp16(smb + (uint32_t)((OFF_V + (s*64+r)*VP + c)*2), vbase + (size_t)r*NN + kv0 + c);
        }
        CP_COMMIT;
    };

    fillkv(0, 0); fillkv(1, 1);

    CP_WAIT2; __syncthreads();
    uint32_t qf[4][4];
#pragma unroll
    for (int kc = 0; kc < 4; kc++)
        ldsm4(qf[kc], smb + qLane + (uint32_t)(kc*32));

    float o[8][4], o_l[4];
#pragma unroll
    for (int i = 0; i < 8; i++)
#pragma unroll
        for (int j = 0; j < 4; j++) o[i][j] = 0.f;
#pragma unroll
    for (int j = 0; j < 4; j++) o_l[j] = 0.f;

    const int NT = NN/64;   // 32
    for (int kt = 0; kt < NT; ++kt){
        CP_WAIT1; __syncthreads();
        int st = kt % 3;
        if (kt + 2 < NT) fillkv(kt + 2, (kt + 2) % 3);
        else             { CP_COMMIT; }

        const uint32_t kA = smb + (uint32_t)((OFF_K + st*64*KP)*2) + bLaneK;
        const uint32_t vA = smb + (uint32_t)((OFF_V + st*64*VP)*2) + bLaneV;

#pragma unroll
        for (int jp2 = 0; jp2 < 2; ++jp2){
            float s[4][4];
#pragma unroll
            for (int i = 0; i < 4; i++)
#pragma unroll
                for (int j = 0; j < 4; j++) s[i][j] = 0.f;
#pragma unroll
            for (int na4 = 0; na4 < 4; ++na4){
                int na = jp2*4 + na4;
                uint32_t bf0[4], bf1[4];
                ldsm4(bf0, kA + (uint32_t)(na*8*KP*2));
                ldsm4(bf1, kA + (uint32_t)(na*8*KP*2 + 64));
                mma16(s[na4], qf[0], bf0);
                mma16(s[na4], qf[1], bf0 + 2);
                mma16(s[na4], qf[2], bf1);
                mma16(s[na4], qf[3], bf1 + 2);
            }

            uint32_t pf[2][4];
            pf[0][0] = h2ex2(h2pack(s[0][0], s[0][1]));
            pf[0][1] = h2ex2(h2pack(s[0][2], s[0][3]));
            pf[0][2] = h2ex2(h2pack(s[1][0], s[1][1]));
            pf[0][3] = h2ex2(h2pack(s[1][2], s[1][3]));
            pf[1][0] = h2ex2(h2pack(s[2][0], s[2][1]));
            pf[1][1] = h2ex2(h2pack(s[2][2], s[2][3]));
            pf[1][2] = h2ex2(h2pack(s[3][0], s[3][1]));
            pf[1][3] = h2ex2(h2pack(s[3][2], s[3][3]));

            mma16(o_l, pf[0], cone);
            mma16(o_l, pf[1], cone);

#pragma unroll
            for (int nb = 0; nb < 8; ++nb){
                uint32_t vf[4];
                ldsm4(vf, vA + (uint32_t)(nb*8*VP*2 + jp2*64));
                mma16(o[nb], pf[0], vf);
                mma16(o[nb], pf[1], vf + 2);
            }
        }
    }

    float l0 = __shfl_sync(0xffffffffu, o_l[0], lane & ~3);
    float l1 = __shfl_sync(0xffffffffu, o_l[2], lane & ~3);
    float inv0 = 1.f / l0, inv1 = 1.f / l1;

    int r0 = b*NN + q0 + wid*16 + g;
#pragma unroll
    for (int na = 0; na < 8; na++){
        int cc = h*HD + na*8 + 2*t;
        *(uint32_t*)&out[(size_t)r0*DIM + cc]     = h2pack(o[na][0]*inv0, o[na][1]*inv0);
        *(uint32_t*)&out[(size_t)(r0+8)*DIM + cc] = h2pack(o[na][2]*inv1, o[na][3]*inv1);
    }
}

// ---------------- launch ----------------
extern "C" void kernel_launch(void* const* d_in, const int* in_sizes, int n_in,
                              void* d_out, int out_size)
{
    const float* x      = (const float*)d_in[0];
    const float* w_qkv  = (const float*)d_in[1];
    const float* w_proj = (const float*)d_in[2];
    const float* b_proj = (const float*)d_in[3];
    const float* w_head = (const float*)d_in[4];
    const float* b_head = (const float*)d_in[5];
    float* out = (float*)d_out;

    __half *qkv, *att, *proj, *vt, *xh, *wqT, *wpT, *whT;
    uint32_t* mxu;
    cudaGetSymbolAddress((void**)&qkv, g_qkv);
    cudaGetSymbolAddress((void**)&att, g_att);
    cudaGetSymbolAddress((void**)&proj, g_proj);
    cudaGetSymbolAddress((void**)&vt,  g_vt);
    cudaGetSymbolAddress((void**)&xh,  g_xh);
    cudaGetSymbolAddress((void**)&wqT, g_wqkvT);
    cudaGetSymbolAddress((void**)&wpT, g_wprojT);
    cudaGetSymbolAddress((void**)&whT, g_wheadT);
    cudaGetSymbolAddress((void**)&mxu, g_maxu);

    cudaFuncSetAttribute(mma_gemm<1>, cudaFuncAttributeMaxDynamicSharedMemorySize, GEMM_SMEM);
    cudaFuncSetAttribute(mma_gemm<2>, cudaFuncAttributeMaxDynamicSharedMemorySize, GEMM_SMEM);
    cudaFuncSetAttribute(mma_gemm<3>, cudaFuncAttributeMaxDynamicSharedMemorySize, GEMM_SMEM);
    cudaFuncSetAttribute(attn_mma,    cudaFuncAttributeMaxDynamicSharedMemorySize, ATT_SMEM);

    // 1) fused preprocessing
    prep<<<NB_TOTAL, 256>>>(x, w_qkv, w_proj, w_head, xh, wqT, wpT, whT, mxu);

    // 2) QKV GEMM — Q,K row-major to qkv; V d-major to vt
    mma_gemm<3><<<dim3(3*DIM/128, MM/128), 256, GEMM_SMEM>>>(
        xh, wqT, nullptr, qkv, nullptr, vt, MM, 3*DIM, DIM);

    // 3) attention
    attn_mma<<<dim3(NN/128, BB*HEADS), 256, ATT_SMEM>>>(qkv, vt, att);

    // 4) proj GEMM
    mma_gemm<1><<<dim3(DIM/128, MM/128), 256, GEMM_SMEM>>>(
        att, wpT, b_proj, proj, nullptr, nullptr, MM, DIM, DIM);

    // 5) head GEMM + fused token-max
    mma_gemm<2><<<dim3(NPAD/128, MM/128), 256, GEMM_SMEM>>>(
        proj, whT, b_head, nullptr, mxu, nullptr, MM, NPAD, DIM);

    // 6) decode
    decode_maxu<<<(BB*NCLS + 255)/256, 256>>>(mxu, out);
}